// round 15
// baseline (speedup 1.0000x reference)
#include <cuda_runtime.h>
#include <cuda_bf16.h>
#include <math.h>
#include <stdint.h>

// Problem constants (fixed by setup_inputs)
#define B_    2
#define S_    1024
#define ROWS  (B_*S_)       // 2048
#define H_    1536
#define F_    8960
#define L_    2
#define NH    12
#define NKV   2
#define DH    128
#define QD    (NH*DH)       // 1536
#define KVD   (NKV*DH)      // 256
#define EPS_  1e-6f
#define QT    16

// Weight-split segment sizes (elements) and per-layer offsets
#define WQ_SZ  (H_*QD)
#define WKV_SZ (H_*KVD)
#define WO_SZ  (QD*H_)
#define WGU_SZ (H_*F_)
#define WD_SZ  (F_*H_)
#define OFF_WQ 0
#define OFF_WK (OFF_WQ + WQ_SZ)
#define OFF_WV (OFF_WK + WKV_SZ)
#define OFF_WO (OFF_WV + WKV_SZ)
#define OFF_WG (OFF_WO + WO_SZ)
#define OFF_WU (OFF_WG + WGU_SZ)
#define OFF_WD (OFF_WU + WGU_SZ)
#define WLAYER (OFF_WD + WD_SZ)

// Scratch (device globals: no allocation allowed)
__device__ float g_x  [ROWS*H_];
__device__ __nv_bfloat16 g_hhi[ROWS*H_];
__device__ __nv_bfloat16 g_hlo[ROWS*H_];
__device__ float g_q  [ROWS*QD];
__device__ float g_k  [ROWS*KVD];
__device__ float g_v  [ROWS*KVD];
__device__ __nv_bfloat16 g_ahi[ROWS*QD];
__device__ __nv_bfloat16 g_alo[ROWS*QD];
__device__ float g_gate[(size_t)ROWS*F_];
__device__ float g_up  [(size_t)ROWS*F_];
__device__ __nv_bfloat16 g_ghi[(size_t)ROWS*F_];
__device__ __nv_bfloat16 g_glo[(size_t)ROWS*F_];
__device__ __nv_bfloat16 g_whi[(size_t)L_*WLAYER];
__device__ __nv_bfloat16 g_wlo[(size_t)L_*WLAYER];

typedef __nv_bfloat16 bf16;

__device__ __forceinline__ void split1(float x, bf16& h, bf16& l) {
    h = __float2bfloat16(x);
    l = __float2bfloat16(x - __bfloat162float(h));
}

// ---------------- weight split + transpose: W[K][N] fp32 -> hi/lo [N][K] bf16 ----------------
__global__ void wsplit_kernel(const float* __restrict__ W, int K, int N,
                              bf16* __restrict__ hi, bf16* __restrict__ lo) {
    __shared__ float t[32][33];
    const int n0 = blockIdx.x * 32, k0 = blockIdx.y * 32;
    const int tx = threadIdx.x, ty = threadIdx.y;   // 32 x 8
    #pragma unroll
    for (int j = 0; j < 4; j++)
        t[ty + 8 * j][tx] = W[(size_t)(k0 + ty + 8 * j) * N + n0 + tx];
    __syncthreads();
    #pragma unroll
    for (int j = 0; j < 4; j++) {
        int n = n0 + ty + 8 * j;
        float v = t[tx][ty + 8 * j];
        bf16 h, l; split1(v, h, l);
        hi[(size_t)n * K + k0 + tx] = h;
        lo[(size_t)n * K + k0 + tx] = l;
    }
}

// ---------------- embedding gather ----------------
__global__ void embed_kernel(const int* __restrict__ ids,
                             const float* __restrict__ emb,
                             float* __restrict__ x) {
    int row = blockIdx.x;
    int id  = ids[row];
    const float* e = emb + (size_t)id * H_;
    float* xr = x + (size_t)row * H_;
    for (int i = threadIdx.x; i < H_; i += blockDim.x) xr[i] = e[i];
}

// ---------------- rmsnorm -> hi/lo bf16 ----------------
__global__ void rmsnorm_split_kernel(const float* __restrict__ x,
                                     const float* __restrict__ w,
                                     bf16* __restrict__ ohi, bf16* __restrict__ olo) {
    int row = blockIdx.x;
    const float* xr = x + (size_t)row * H_;
    int tid = threadIdx.x;            // 256
    float s = 0.f;
    for (int i = tid; i < H_; i += 256) { float v = xr[i]; s += v * v; }
    __shared__ float red[256];
    red[tid] = s; __syncthreads();
    for (int off = 128; off > 0; off >>= 1) {
        if (tid < off) red[tid] += red[tid + off];
        __syncthreads();
    }
    float rs = rsqrtf(red[0] / (float)H_ + EPS_);
    for (int i = tid; i < H_; i += 256) {
        float v = xr[i] * rs * w[i];
        bf16 h, l; split1(v, h, l);
        ohi[(size_t)row * H_ + i] = h;
        olo[(size_t)row * H_ + i] = l;
    }
}

// ---------------- rmsnorm -> fp32 (final) ----------------
__global__ void rmsnorm_kernel(const float* __restrict__ x,
                               const float* __restrict__ w,
                               float* __restrict__ out) {
    int row = blockIdx.x;
    const float* xr = x + (size_t)row * H_;
    int tid = threadIdx.x;
    float s = 0.f;
    for (int i = tid; i < H_; i += 256) { float v = xr[i]; s += v * v; }
    __shared__ float red[256];
    red[tid] = s; __syncthreads();
    for (int off = 128; off > 0; off >>= 1) {
        if (tid < off) red[tid] += red[tid + off];
        __syncthreads();
    }
    float rs = rsqrtf(red[0] / (float)H_ + EPS_);
    float* o = out + (size_t)row * H_;
    for (int i = tid; i < H_; i += 256) o[i] = xr[i] * rs * w[i];
}

// ---------------- MMA + cp.async + ldmatrix helpers ----------------
__device__ __forceinline__ void mma_bf16(float c[4], const uint32_t a[4], const uint32_t b[2]) {
    asm volatile(
        "mma.sync.aligned.m16n8k16.row.col.f32.bf16.bf16.f32 "
        "{%0,%1,%2,%3}, {%4,%5,%6,%7}, {%8,%9}, {%0,%1,%2,%3};"
        : "+f"(c[0]), "+f"(c[1]), "+f"(c[2]), "+f"(c[3])
        : "r"(a[0]), "r"(a[1]), "r"(a[2]), "r"(a[3]), "r"(b[0]), "r"(b[1]));
}

__device__ __forceinline__ void cp16(void* s, const void* g) {
    uint32_t sa = (uint32_t)__cvta_generic_to_shared(s);
    asm volatile("cp.async.cg.shared.global [%0], [%1], 16;" :: "r"(sa), "l"(g));
}

__device__ __forceinline__ void ldm_x4(uint32_t& r0, uint32_t& r1, uint32_t& r2, uint32_t& r3,
                                       uint32_t addr) {
    asm volatile("ldmatrix.sync.aligned.m8n8.x4.shared.b16 {%0,%1,%2,%3}, [%4];"
                 : "=r"(r0), "=r"(r1), "=r"(r2), "=r"(r3) : "r"(addr));
}

// ---------------- bf16x3 GEMM body: 512 threads, BM=128, BN=256, BK=64 ----------------
// 16 warps, 4x4 grid, warp tile 32x64 -> 12 ldm per 48 MMAs per k16 (1.33x less smem traffic).
#define TSTRIDE 144
#define A_TILE_B (128 * TSTRIDE)          // 18432 per tensor
#define B_TILE_B (256 * TSTRIDE)          // 36864 per tensor
#define STAGE_B (2 * A_TILE_B + 2 * B_TILE_B)   // 110592
#define SMEM_BYTES (2 * STAGE_B)                // 221184
#define T_AHI 0
#define T_ALO A_TILE_B
#define T_BHI (2 * A_TILE_B)
#define T_BLO (2 * A_TILE_B + B_TILE_B)

template<bool BIAS, bool RES>
__device__ __forceinline__ void
gemm_body(int K, int ldc,
          const bf16* __restrict__ Ahi, const bf16* __restrict__ Alo,   // + rowblock*K
          const bf16* __restrict__ Bhi, const bf16* __restrict__ Blo,   // + n0*K
          const float* __restrict__ bias,                               // + n0
          const float* __restrict__ res,                                // + rowblock*ldc + n0
          float* __restrict__ C,                                        // + rowblock*ldc + n0
          char* smem) {
    const int tid  = threadIdx.x;       // 512
    const int lane = tid & 31;
    const int wid  = tid >> 5;
    const int wm   = wid & 3;           // 0..3 : 32-row slab
    const int wn   = wid >> 2;          // 0..3 : 64-col slab

    // staging: A (128 rows): 4 threads/row, 2 chunks each; B (256 rows): 2 threads/row, 4 chunks each
    const int arow = tid >> 2;
    const size_t gA = (size_t)arow * K + (tid & 3) * 16;
    const uint32_t sA = (uint32_t)(arow * TSTRIDE + (tid & 3) * 32);
    const int brow = tid >> 1;
    const size_t gB = (size_t)brow * K + (tid & 1) * 32;
    const uint32_t sB = (uint32_t)(brow * TSTRIDE + (tid & 1) * 64);

    const uint32_t smemBase = (uint32_t)__cvta_generic_to_shared(smem);

    // ldmatrix lane mappings
    const int lj = lane >> 3;
    const int lr = lane & 7;
    uint32_t aoff[2];
    #pragma unroll
    for (int m = 0; m < 2; m++)
        aoff[m] = (uint32_t)((wm * 32 + m * 16 + (lj & 1) * 8 + lr) * TSTRIDE + (lj >> 1) * 16);
    uint32_t boff[4];
    #pragma unroll
    for (int p = 0; p < 4; p++)
        boff[p] = (uint32_t)((wn * 64 + p * 16 + (lj >> 1) * 8 + lr) * TSTRIDE + (lj & 1) * 16);

    float acc[2][8][4];
    #pragma unroll
    for (int m = 0; m < 2; m++)
        #pragma unroll
        for (int n = 0; n < 8; n++)
            #pragma unroll
            for (int r = 0; r < 4; r++) acc[m][n][r] = 0.f;

    const int NT = K / 64;

    // prologue: stage 0
    #pragma unroll
    for (int c = 0; c < 2; c++) {
        cp16(smem + T_AHI + sA + c * 16, Ahi + gA + c * 8);
        cp16(smem + T_ALO + sA + c * 16, Alo + gA + c * 8);
    }
    #pragma unroll
    for (int c = 0; c < 4; c++) {
        cp16(smem + T_BHI + sB + c * 16, Bhi + gB + c * 8);
        cp16(smem + T_BLO + sB + c * 16, Blo + gB + c * 8);
    }
    asm volatile("cp.async.commit_group;");

    for (int t = 0; t < NT; t++) {
        if (t + 1 < NT) {
            char* s1 = smem + ((t + 1) & 1) * STAGE_B;
            const size_t adv = (size_t)(t + 1) * 64;
            #pragma unroll
            for (int c = 0; c < 2; c++) {
                cp16(s1 + T_AHI + sA + c * 16, Ahi + gA + adv + c * 8);
                cp16(s1 + T_ALO + sA + c * 16, Alo + gA + adv + c * 8);
            }
            #pragma unroll
            for (int c = 0; c < 4; c++) {
                cp16(s1 + T_BHI + sB + c * 16, Bhi + gB + adv + c * 8);
                cp16(s1 + T_BLO + sB + c * 16, Blo + gB + adv + c * 8);
            }
            asm volatile("cp.async.commit_group;");
            asm volatile("cp.async.wait_group 1;");
        } else {
            asm volatile("cp.async.wait_group 0;");
        }
        __syncthreads();

        const uint32_t sb = smemBase + (t & 1) * STAGE_B;

        #pragma unroll
        for (int ks = 0; ks < 4; ks++) {
            const uint32_t kb = ks * 32;
            uint32_t ah[2][4], al[2][4];
            #pragma unroll
            for (int m = 0; m < 2; m++) {
                ldm_x4(ah[m][0], ah[m][1], ah[m][2], ah[m][3], sb + T_AHI + aoff[m] + kb);
                ldm_x4(al[m][0], al[m][1], al[m][2], al[m][3], sb + T_ALO + aoff[m] + kb);
            }
            #pragma unroll
            for (int p = 0; p < 4; p++) {
                uint32_t bh0[2], bh1[2], bl0[2], bl1[2];
                ldm_x4(bh0[0], bh0[1], bh1[0], bh1[1], sb + T_BHI + boff[p] + kb);
                ldm_x4(bl0[0], bl0[1], bl1[0], bl1[1], sb + T_BLO + boff[p] + kb);
                #pragma unroll
                for (int m = 0; m < 2; m++) {
                    mma_bf16(acc[m][2*p],   ah[m], bh0);
                    mma_bf16(acc[m][2*p],   al[m], bh0);
                    mma_bf16(acc[m][2*p],   ah[m], bl0);
                    mma_bf16(acc[m][2*p+1], ah[m], bh1);
                    mma_bf16(acc[m][2*p+1], al[m], bh1);
                    mma_bf16(acc[m][2*p+1], ah[m], bl1);
                }
            }
        }
        __syncthreads();
    }

    // epilogue
    const int fr  = lane >> 2;
    const int fc2 = (lane & 3) * 2;
    #pragma unroll
    for (int m = 0; m < 2; m++) {
        int row0 = wm * 32 + m * 16 + fr;
        #pragma unroll
        for (int n = 0; n < 8; n++) {
            int col = wn * 64 + n * 8 + fc2;
            float v0 = acc[m][n][0], v1 = acc[m][n][1];
            float v2 = acc[m][n][2], v3 = acc[m][n][3];
            if (BIAS) {
                float b0 = bias[col], b1 = bias[col + 1];
                v0 += b0; v1 += b1; v2 += b0; v3 += b1;
            }
            if (RES) {
                v0 += res[(size_t)row0 * ldc + col];
                v1 += res[(size_t)row0 * ldc + col + 1];
                v2 += res[(size_t)(row0 + 8) * ldc + col];
                v3 += res[(size_t)(row0 + 8) * ldc + col + 1];
            }
            C[(size_t)row0 * ldc + col]           = v0;
            C[(size_t)row0 * ldc + col + 1]       = v1;
            C[(size_t)(row0 + 8) * ldc + col]     = v2;
            C[(size_t)(row0 + 8) * ldc + col + 1] = v3;
        }
    }
}

// generic GEMM with residual (o-proj K=QD, down-proj K=F), N=H, BN=256
__global__ void __launch_bounds__(512, 1)
mma_gemm_res(int K,
             const bf16* __restrict__ Ahi, const bf16* __restrict__ Alo,
             const bf16* __restrict__ Whi, const bf16* __restrict__ Wlo,
             const float* __restrict__ res, float* __restrict__ C) {
    extern __shared__ char smem[];
    const int bx = blockIdx.x, by = blockIdx.y;
    gemm_body<false, true>(K, H_,
                           Ahi + (size_t)by * 128 * K, Alo + (size_t)by * 128 * K,
                           Whi + (size_t)bx * 256 * K, Wlo + (size_t)bx * 256 * K,
                           nullptr,
                           res + (size_t)by * 128 * H_ + bx * 256,
                           C + (size_t)by * 128 * H_ + bx * 256,
                           smem);
}

// fused QKV projection: grid.x = 8 (6 q blocks of 256, 1 k, 1 v); K = H
__global__ void __launch_bounds__(512, 1)
qkv_kernel(const bf16* __restrict__ Ahi, const bf16* __restrict__ Alo,
           const bf16* __restrict__ whi, const bf16* __restrict__ wlo,   // layer base
           const float* __restrict__ bq, const float* __restrict__ bk,
           const float* __restrict__ bv,
           float* __restrict__ q, float* __restrict__ k, float* __restrict__ v) {
    extern __shared__ char smem[];
    const int bx = blockIdx.x, by = blockIdx.y;
    size_t seg; const float* bp; float* Cp; int ld, n0;
    if (bx < 6)       { seg = OFF_WQ; n0 = bx * 256; bp = bq; Cp = q; ld = QD;  }
    else if (bx == 6) { seg = OFF_WK; n0 = 0;        bp = bk; Cp = k; ld = KVD; }
    else              { seg = OFF_WV; n0 = 0;        bp = bv; Cp = v; ld = KVD; }
    gemm_body<true, false>(H_, ld,
                           Ahi + (size_t)by * 128 * H_, Alo + (size_t)by * 128 * H_,
                           whi + seg + (size_t)n0 * H_, wlo + seg + (size_t)n0 * H_,
                           bp + n0, nullptr,
                           Cp + (size_t)by * 128 * ld + n0,
                           smem);
}

// fused gate+up projection: grid.x = 70 (35 gate, 35 up); K = H, ldc = F, BN=256
__global__ void __launch_bounds__(512, 1)
gateup_kernel(const bf16* __restrict__ Ahi, const bf16* __restrict__ Alo,
              const bf16* __restrict__ whi, const bf16* __restrict__ wlo,  // layer base
              float* __restrict__ gate, float* __restrict__ up) {
    extern __shared__ char smem[];
    const int bx = blockIdx.x, by = blockIdx.y;
    size_t seg; float* Cp; int n0;
    if (bx < 35) { seg = OFF_WG; n0 = bx * 256;        Cp = gate; }
    else         { seg = OFF_WU; n0 = (bx - 35) * 256; Cp = up;   }
    gemm_body<false, false>(H_, F_,
                            Ahi + (size_t)by * 128 * H_, Alo + (size_t)by * 128 * H_,
                            whi + seg + (size_t)n0 * H_, wlo + seg + (size_t)n0 * H_,
                            nullptr, nullptr,
                            Cp + (size_t)by * 128 * F_ + n0,
                            smem);
}

// ---------------- RoPE (in place) ----------------
__global__ void rope_kernel(float* __restrict__ t, int nh) {
    int row = blockIdx.x;
    int tid = threadIdx.x;          // nh*64
    int hh = tid >> 6, d = tid & 63;
    int s = row % S_;
    float inv = expf(-(float)d * (13.815510557964274f / 64.0f));
    float ang = (float)s * inv;
    float sn, cs; sincosf(ang, &sn, &cs);
    float* p = t + (size_t)row * (nh * DH) + hh * DH + d;
    float x0 = p[0], x1 = p[64];
    p[0]  = x0 * cs - x1 * sn;
    p[64] = x1 * cs + x0 * sn;
}

// ---------------- attention: one block per (b, head, 16 q-rows), 128 threads ----------------
__global__ void __launch_bounds__(128, 3)
attn_kernel(const float* __restrict__ q,
            const float* __restrict__ k,
            const float* __restrict__ v,
            const int* __restrict__ mask,
            bf16* __restrict__ ohi, bf16* __restrict__ olo) {
    const int NQB = S_ / QT;             // 64
    int blk = blockIdx.x;
    int b   = blk / (NH * NQB);
    int rem = blk % (NH * NQB);
    int h   = rem / NQB;
    int q0  = (rem % NQB) * QT;
    int kvh = h / (NH / NKV);
    int tid = threadIdx.x;               // 128
    int lane = tid & 31, wrp = tid >> 5;

    __shared__ float qs[QT][DH];
    __shared__ float sc[QT][128];
    __shared__ float redm[QT][4];
    __shared__ float reds[QT][4];

    #pragma unroll
    for (int r = 0; r < QT; r++)
        qs[r][tid] = q[((size_t)(b * S_ + q0 + r)) * QD + h * DH + tid];
    __syncthreads();

    float m[QT], l[QT], acc[QT];
    #pragma unroll
    for (int r = 0; r < QT; r++) { m[r] = -1e30f; l[r] = 0.f; acc[r] = 0.f; }

    const float scale = 0.08838834764831845f;
    const int kend = q0 + QT;

    for (int kc = 0; kc < kend; kc += 128) {
        int j = kc + tid;
        bool jvalid = (j < kend) && (mask[b * S_ + j] > 0);
        float s[QT];
        if (jvalid) {
            const float4* kr = (const float4*)(k + ((size_t)(b * S_ + j)) * KVD + kvh * DH);
            float sum[QT];
            #pragma unroll
            for (int r = 0; r < QT; r++) sum[r] = 0.f;
            #pragma unroll 8
            for (int t4 = 0; t4 < 32; t4++) {
                float4 kk = kr[t4];
                #pragma unroll
                for (int r = 0; r < QT; r++) {
                    float4 qq = *(const float4*)&qs[r][t4 * 4];
                    sum[r] += qq.x * kk.x + qq.y * kk.y + qq.z * kk.z + qq.w * kk.w;
                }
            }
            #pragma unroll
            for (int r = 0; r < QT; r++)
                s[r] = (j <= q0 + r) ? sum[r] * scale : -1e30f;
        } else {
            #pragma unroll
            for (int r = 0; r < QT; r++) s[r] = -1e30f;
        }

        #pragma unroll
        for (int r = 0; r < QT; r++) {
            float wm = s[r];
            #pragma unroll
            for (int off = 16; off > 0; off >>= 1)
                wm = fmaxf(wm, __shfl_xor_sync(0xFFFFFFFF, wm, off));
            if (lane == 0) redm[r][wrp] = wm;
        }
        __syncthreads();

        float aph[QT];
        #pragma unroll
        for (int r = 0; r < QT; r++) {
            float cmax = fmaxf(fmaxf(redm[r][0], redm[r][1]), fmaxf(redm[r][2], redm[r][3]));
            float mnew = fmaxf(m[r], cmax);
            float pp = (s[r] > -1e29f) ? __expf(s[r] - mnew) : 0.f;
            sc[r][tid] = pp;
            float ws = pp;
            #pragma unroll
            for (int off = 16; off > 0; off >>= 1)
                ws += __shfl_xor_sync(0xFFFFFFFF, ws, off);
            if (lane == 0) reds[r][wrp] = ws;
            aph[r] = __expf(m[r] - mnew);
            m[r] = mnew;
        }
        __syncthreads();

        #pragma unroll
        for (int r = 0; r < QT; r++) {
            float psum = reds[r][0] + reds[r][1] + reds[r][2] + reds[r][3];
            l[r] = l[r] * aph[r] + psum;
            acc[r] *= aph[r];
        }

        int len = min(128, kend - kc);
        const float* vb = v + ((size_t)(b * S_ + kc)) * KVD + kvh * DH + tid;
        for (int jj = 0; jj < len; jj++) {
            float vv = vb[(size_t)jj * KVD];
            #pragma unroll
            for (int r = 0; r < QT; r++) acc[r] += sc[r][jj] * vv;
        }
        __syncthreads();
    }

    #pragma unroll
    for (int r = 0; r < QT; r++) {
        float o = acc[r] / l[r];
        bf16 hh2, ll2; split1(o, hh2, ll2);
        size_t idx = ((size_t)(b * S_ + q0 + r)) * QD + h * DH + tid;
        ohi[idx] = hh2;
        olo[idx] = ll2;
    }
}

// ---------------- silu(gate) * up -> hi/lo bf16 ----------------
__global__ void silu_mul_kernel(const float* __restrict__ g, const float* __restrict__ u,
                                bf16* __restrict__ ohi, bf16* __restrict__ olo, size_t n) {
    size_t i = (size_t)blockIdx.x * blockDim.x + threadIdx.x;
    if (i < n) {
        float x = g[i];
        float s = x / (1.f + __expf(-x));
        float v = s * u[i];
        bf16 h, l; split1(v, h, l);
        ohi[i] = h; olo[i] = l;
    }
}

// ---------------- last_hidden gather ----------------
__global__ void last_kernel(const int* __restrict__ mask,
                            const float* __restrict__ hidden,
                            float* __restrict__ out) {
    int b = blockIdx.x;
    int tid = threadIdx.x;  // 256
    __shared__ int red[256];
    int s = 0;
    for (int i = tid; i < S_; i += 256) s += mask[b * S_ + i];
    red[tid] = s; __syncthreads();
    for (int off = 128; off > 0; off >>= 1) {
        if (tid < off) red[tid] += red[tid + off];
        __syncthreads();
    }
    int pos = red[0] - 1;
    const float* hr = hidden + ((size_t)(b * S_ + pos)) * H_;
    for (int i = tid; i < H_; i += 256) out[(size_t)b * H_ + i] = hr[i];
}

extern "C" void kernel_launch(void* const* d_in, const int* in_sizes, int n_in,
                              void* d_out, int out_size) {
    const int*   ids  = (const int*)d_in[0];
    const int*   mask = (const int*)d_in[1];
    const float* emb  = (const float*)d_in[2];
    const float* wq   = (const float*)d_in[3];
    const float* bq   = (const float*)d_in[4];
    const float* wk   = (const float*)d_in[5];
    const float* bk   = (const float*)d_in[6];
    const float* wv   = (const float*)d_in[7];
    const float* bv   = (const float*)d_in[8];
    const float* wo   = (const float*)d_in[9];
    const float* wg   = (const float*)d_in[10];
    const float* wu   = (const float*)d_in[11];
    const float* wd   = (const float*)d_in[12];
    const float* ln1  = (const float*)d_in[13];
    const float* ln2  = (const float*)d_in[14];
    const float* lnf  = (const float*)d_in[15];
    float* out = (float*)d_out;

    float *x, *q, *k, *v, *gate, *up;
    bf16 *hhi, *hlo, *ahi, *alo, *ghi, *glo, *whi, *wlo;
    cudaGetSymbolAddress((void**)&x,    g_x);
    cudaGetSymbolAddress((void**)&hhi,  g_hhi);
    cudaGetSymbolAddress((void**)&hlo,  g_hlo);
    cudaGetSymbolAddress((void**)&q,    g_q);
    cudaGetSymbolAddress((void**)&k,    g_k);
    cudaGetSymbolAddress((void**)&v,    g_v);
    cudaGetSymbolAddress((void**)&ahi,  g_ahi);
    cudaGetSymbolAddress((void**)&alo,  g_alo);
    cudaGetSymbolAddress((void**)&gate, g_gate);
    cudaGetSymbolAddress((void**)&up,   g_up);
    cudaGetSymbolAddress((void**)&ghi,  g_ghi);
    cudaGetSymbolAddress((void**)&glo,  g_glo);
    cudaGetSymbolAddress((void**)&whi,  g_whi);
    cudaGetSymbolAddress((void**)&wlo,  g_wlo);

    static bool attr_set = false;
    if (!attr_set) {
        cudaFuncSetAttribute(qkv_kernel,
                             cudaFuncAttributeMaxDynamicSharedMemorySize, SMEM_BYTES);
        cudaFuncSetAttribute(gateup_kernel,
                             cudaFuncAttributeMaxDynamicSharedMemorySize, SMEM_BYTES);
        cudaFuncSetAttribute(mma_gemm_res,
                             cudaFuncAttributeMaxDynamicSharedMemorySize, SMEM_BYTES);
        attr_set = true;
    }

    // pre-split + transpose all weights (constant inputs)
    dim3 wb(32, 8);
    for (int l = 0; l < L_; l++) {
        bf16* Whi = whi + (size_t)l * WLAYER;
        bf16* Wlo = wlo + (size_t)l * WLAYER;
        wsplit_kernel<<<dim3(QD / 32, H_ / 32), wb>>>(wq + (size_t)l * H_ * QD,  H_, QD,  Whi + OFF_WQ, Wlo + OFF_WQ);
        wsplit_kernel<<<dim3(KVD / 32, H_ / 32), wb>>>(wk + (size_t)l * H_ * KVD, H_, KVD, Whi + OFF_WK, Wlo + OFF_WK);
        wsplit_kernel<<<dim3(KVD / 32, H_ / 32), wb>>>(wv + (size_t)l * H_ * KVD, H_, KVD, Whi + OFF_WV, Wlo + OFF_WV);
        wsplit_kernel<<<dim3(H_ / 32, QD / 32), wb>>>(wo + (size_t)l * QD * H_,  QD, H_,  Whi + OFF_WO, Wlo + OFF_WO);
        wsplit_kernel<<<dim3(F_ / 32, H_ / 32), wb>>>(wg + (size_t)l * H_ * F_,  H_, F_,  Whi + OFF_WG, Wlo + OFF_WG);
        wsplit_kernel<<<dim3(F_ / 32, H_ / 32), wb>>>(wu + (size_t)l * H_ * F_,  H_, F_,  Whi + OFF_WU, Wlo + OFF_WU);
        wsplit_kernel<<<dim3(H_ / 32, F_ / 32), wb>>>(wd + (size_t)l * F_ * H_,  F_, H_,  Whi + OFF_WD, Wlo + OFF_WD);
    }

    embed_kernel<<<ROWS, 256>>>(ids, emb, x);

    for (int l = 0; l < L_; l++) {
        const bf16* Whi = whi + (size_t)l * WLAYER;
        const bf16* Wlo = wlo + (size_t)l * WLAYER;

        rmsnorm_split_kernel<<<ROWS, 256>>>(x, ln1 + (size_t)l * H_, hhi, hlo);

        qkv_kernel<<<dim3(8, ROWS / 128), 512, SMEM_BYTES>>>(
            hhi, hlo, Whi, Wlo,
            bq + (size_t)l * QD, bk + (size_t)l * KVD, bv + (size_t)l * KVD,
            q, k, v);

        rope_kernel<<<ROWS, NH * 64>>>(q, NH);
        rope_kernel<<<ROWS, NKV * 64>>>(k, NKV);

        attn_kernel<<<B_ * NH * (S_ / QT), 128>>>(q, k, v, mask, ahi, alo);

        mma_gemm_res<<<dim3(H_ / 256, ROWS / 128), 512, SMEM_BYTES>>>(
            QD, ahi, alo, Whi + OFF_WO, Wlo + OFF_WO, x, x);

        rmsnorm_split_kernel<<<ROWS, 256>>>(x, ln2 + (size_t)l * H_, hhi, hlo);

        gateup_kernel<<<dim3(70, ROWS / 128), 512, SMEM_BYTES>>>(
            hhi, hlo, Whi, Wlo, gate, up);

        silu_mul_kernel<<<((size_t)ROWS * F_ + 255) / 256, 256>>>(
            gate, up, ghi, glo, (size_t)ROWS * F_);

        mma_gemm_res<<<dim3(H_ / 256, ROWS / 128), 512, SMEM_BYTES>>>(
            F_, ghi, glo, Whi + OFF_WD, Wlo + OFF_WD, x, x);
    }

    rmsnorm_kernel<<<ROWS, 256>>>(x, lnf, out);
    last_kernel<<<B_, 256>>>(mask, out, out + (size_t)ROWS * H_);
}

// round 17
// speedup vs baseline: 1.0525x; 1.0525x over previous
#include <cuda_runtime.h>
#include <cuda_bf16.h>
#include <math.h>
#include <stdint.h>

// Problem constants (fixed by setup_inputs)
#define B_    2
#define S_    1024
#define ROWS  (B_*S_)       // 2048
#define H_    1536
#define F_    8960
#define L_    2
#define NH    12
#define NKV   2
#define DH    128
#define QD    (NH*DH)       // 1536
#define KVD   (NKV*DH)      // 256
#define EPS_  1e-6f
#define QT    16

// Weight-split segment sizes (elements) and per-layer offsets
#define WQ_SZ  (H_*QD)
#define WKV_SZ (H_*KVD)
#define WO_SZ  (QD*H_)
#define WGU_SZ (H_*F_)
#define WD_SZ  (F_*H_)
#define OFF_WQ 0
#define OFF_WK (OFF_WQ + WQ_SZ)
#define OFF_WV (OFF_WK + WKV_SZ)
#define OFF_WO (OFF_WV + WKV_SZ)
#define OFF_WG (OFF_WO + WO_SZ)
#define OFF_WU (OFF_WG + WGU_SZ)
#define OFF_WD (OFF_WU + WGU_SZ)
#define WLAYER (OFF_WD + WD_SZ)

// Scratch (device globals: no allocation allowed)
__device__ float g_x  [ROWS*H_];
__device__ __nv_bfloat16 g_hhi[ROWS*H_];
__device__ __nv_bfloat16 g_hlo[ROWS*H_];
__device__ float g_q  [ROWS*QD];
__device__ float g_k  [ROWS*KVD];
__device__ float g_v  [ROWS*KVD];
__device__ __nv_bfloat16 g_ahi[ROWS*QD];
__device__ __nv_bfloat16 g_alo[ROWS*QD];
__device__ __nv_bfloat16 g_ghi[(size_t)ROWS*F_];
__device__ __nv_bfloat16 g_glo[(size_t)ROWS*F_];
__device__ __nv_bfloat16 g_whi[(size_t)L_*WLAYER];
__device__ __nv_bfloat16 g_wlo[(size_t)L_*WLAYER];

typedef __nv_bfloat16 bf16;

__device__ __forceinline__ void split1(float x, bf16& h, bf16& l) {
    h = __float2bfloat16(x);
    l = __float2bfloat16(x - __bfloat162float(h));
}

__device__ __forceinline__ uint32_t pack2(bf16 a, bf16 b) {
    __nv_bfloat162 t = __halves2bfloat162(a, b);
    uint32_t u; memcpy(&u, &t, 4); return u;
}

// ---------------- weight split + transpose: W[K][N] fp32 -> hi/lo [N][K] bf16 ----------------
// tile k=64 x n=32; packed uint32 stores (2 bf16) -> 128B coalesced per warp.
__global__ void wsplit_kernel(const float* __restrict__ W, int K, int N,
                              bf16* __restrict__ hi, bf16* __restrict__ lo) {
    __shared__ float t[64][33];
    const int n0 = blockIdx.x * 32, k0 = blockIdx.y * 64;
    const int tx = threadIdx.x, ty = threadIdx.y;   // 32 x 8
    #pragma unroll
    for (int j = 0; j < 8; j++)
        t[ty + 8 * j][tx] = W[(size_t)(k0 + ty + 8 * j) * N + n0 + tx];
    __syncthreads();
    #pragma unroll
    for (int j = 0; j < 4; j++) {
        int n = n0 + ty + 8 * j;
        float a = t[2 * tx][ty + 8 * j];
        float b = t[2 * tx + 1][ty + 8 * j];
        bf16 ah, al, bh, bl; split1(a, ah, al); split1(b, bh, bl);
        *(uint32_t*)(hi + (size_t)n * K + k0 + 2 * tx) = pack2(ah, bh);
        *(uint32_t*)(lo + (size_t)n * K + k0 + 2 * tx) = pack2(al, bl);
    }
}

// ---------------- embedding gather ----------------
__global__ void embed_kernel(const int* __restrict__ ids,
                             const float* __restrict__ emb,
                             float* __restrict__ x) {
    int row = blockIdx.x;
    int id  = ids[row];
    const float* e = emb + (size_t)id * H_;
    float* xr = x + (size_t)row * H_;
    for (int i = threadIdx.x; i < H_; i += blockDim.x) xr[i] = e[i];
}

// ---------------- rmsnorm -> hi/lo bf16 ----------------
__global__ void rmsnorm_split_kernel(const float* __restrict__ x,
                                     const float* __restrict__ w,
                                     bf16* __restrict__ ohi, bf16* __restrict__ olo) {
    int row = blockIdx.x;
    const float* xr = x + (size_t)row * H_;
    int tid = threadIdx.x;            // 256
    float s = 0.f;
    for (int i = tid; i < H_; i += 256) { float v = xr[i]; s += v * v; }
    __shared__ float red[256];
    red[tid] = s; __syncthreads();
    for (int off = 128; off > 0; off >>= 1) {
        if (tid < off) red[tid] += red[tid + off];
        __syncthreads();
    }
    float rs = rsqrtf(red[0] / (float)H_ + EPS_);
    for (int i = tid; i < H_; i += 256) {
        float v = xr[i] * rs * w[i];
        bf16 h, l; split1(v, h, l);
        ohi[(size_t)row * H_ + i] = h;
        olo[(size_t)row * H_ + i] = l;
    }
}

// ---------------- rmsnorm -> fp32 (final) ----------------
__global__ void rmsnorm_kernel(const float* __restrict__ x,
                               const float* __restrict__ w,
                               float* __restrict__ out) {
    int row = blockIdx.x;
    const float* xr = x + (size_t)row * H_;
    int tid = threadIdx.x;
    float s = 0.f;
    for (int i = tid; i < H_; i += 256) { float v = xr[i]; s += v * v; }
    __shared__ float red[256];
    red[tid] = s; __syncthreads();
    for (int off = 128; off > 0; off >>= 1) {
        if (tid < off) red[tid] += red[tid + off];
        __syncthreads();
    }
    float rs = rsqrtf(red[0] / (float)H_ + EPS_);
    float* o = out + (size_t)row * H_;
    for (int i = tid; i < H_; i += 256) o[i] = xr[i] * rs * w[i];
}

// ---------------- MMA + cp.async + ldmatrix helpers ----------------
__device__ __forceinline__ void mma_bf16(float c[4], const uint32_t a[4], const uint32_t b[2]) {
    asm volatile(
        "mma.sync.aligned.m16n8k16.row.col.f32.bf16.bf16.f32 "
        "{%0,%1,%2,%3}, {%4,%5,%6,%7}, {%8,%9}, {%0,%1,%2,%3};"
        : "+f"(c[0]), "+f"(c[1]), "+f"(c[2]), "+f"(c[3])
        : "r"(a[0]), "r"(a[1]), "r"(a[2]), "r"(a[3]), "r"(b[0]), "r"(b[1]));
}

__device__ __forceinline__ void cp16(void* s, const void* g) {
    uint32_t sa = (uint32_t)__cvta_generic_to_shared(s);
    asm volatile("cp.async.cg.shared.global [%0], [%1], 16;" :: "r"(sa), "l"(g));
}

__device__ __forceinline__ void ldm_x4(uint32_t& r0, uint32_t& r1, uint32_t& r2, uint32_t& r3,
                                       uint32_t addr) {
    asm volatile("ldmatrix.sync.aligned.m8n8.x4.shared.b16 {%0,%1,%2,%3}, [%4];"
                 : "=r"(r0), "=r"(r1), "=r"(r2), "=r"(r3) : "r"(addr));
}

// ---------------- bf16x3 GEMM body (R13 config): 512 threads, BM=BN=128, BK=64 ----------------
#define TSTRIDE 144
#define TILE_B (128 * TSTRIDE)            // 18432
#define STAGE_B (4 * TILE_B)              // 73728
#define SMEM_BYTES (2 * STAGE_B)          // 147456
#define T_AHI 0
#define T_ALO TILE_B
#define T_BHI (2 * TILE_B)
#define T_BLO (3 * TILE_B)

template<bool BIAS, bool RES>
__device__ __forceinline__ void
gemm_body(int K, int ldc,
          const bf16* __restrict__ Ahi, const bf16* __restrict__ Alo,
          const bf16* __restrict__ Bhi, const bf16* __restrict__ Blo,
          const float* __restrict__ bias,
          const float* __restrict__ res,
          float* __restrict__ C,
          char* smem) {
    const int tid  = threadIdx.x;
    const int lane = tid & 31;
    const int wid  = tid >> 5;
    const int wm   = wid & 3;
    const int wn   = wid >> 2;

    const int row = tid >> 2;
    const int ch  = tid & 3;
    const size_t gRow = (size_t)row * K + ch * 8;
    const uint32_t sOff = (uint32_t)(row * TSTRIDE + ch * 16);

    const uint32_t smemBase = (uint32_t)__cvta_generic_to_shared(smem);

    const int lj = lane >> 3;
    const int lr = lane & 7;
    uint32_t aoff[2];
    #pragma unroll
    for (int m = 0; m < 2; m++)
        aoff[m] = (uint32_t)((wm * 32 + m * 16 + (lj & 1) * 8 + lr) * TSTRIDE + (lj >> 1) * 16);
    uint32_t boff[2];
    #pragma unroll
    for (int p = 0; p < 2; p++)
        boff[p] = (uint32_t)((wn * 32 + p * 16 + (lj >> 1) * 8 + lr) * TSTRIDE + (lj & 1) * 16);

    float acc[2][4][4];
    #pragma unroll
    for (int m = 0; m < 2; m++)
        #pragma unroll
        for (int n = 0; n < 4; n++)
            #pragma unroll
            for (int r = 0; r < 4; r++) acc[m][n][r] = 0.f;

    const int NT = K / 64;

    #pragma unroll
    for (int c = 0; c < 2; c++) {
        cp16(smem + T_AHI + sOff + c * 64, Ahi + gRow + c * 32);
        cp16(smem + T_ALO + sOff + c * 64, Alo + gRow + c * 32);
        cp16(smem + T_BHI + sOff + c * 64, Bhi + gRow + c * 32);
        cp16(smem + T_BLO + sOff + c * 64, Blo + gRow + c * 32);
    }
    asm volatile("cp.async.commit_group;");

    for (int t = 0; t < NT; t++) {
        if (t + 1 < NT) {
            char* s1 = smem + ((t + 1) & 1) * STAGE_B;
            size_t g1 = gRow + (size_t)(t + 1) * 64;
            #pragma unroll
            for (int c = 0; c < 2; c++) {
                cp16(s1 + T_AHI + sOff + c * 64, Ahi + g1 + c * 32);
                cp16(s1 + T_ALO + sOff + c * 64, Alo + g1 + c * 32);
                cp16(s1 + T_BHI + sOff + c * 64, Bhi + g1 + c * 32);
                cp16(s1 + T_BLO + sOff + c * 64, Blo + g1 + c * 32);
            }
            asm volatile("cp.async.commit_group;");
            asm volatile("cp.async.wait_group 1;");
        } else {
            asm volatile("cp.async.wait_group 0;");
        }
        __syncthreads();

        const uint32_t sb = smemBase + (t & 1) * STAGE_B;

        #pragma unroll
        for (int ks = 0; ks < 4; ks++) {
            const uint32_t kb = ks * 32;
            uint32_t ah[2][4], al[2][4], bh[4][2], bl[4][2];
            #pragma unroll
            for (int m = 0; m < 2; m++) {
                ldm_x4(ah[m][0], ah[m][1], ah[m][2], ah[m][3], sb + T_AHI + aoff[m] + kb);
                ldm_x4(al[m][0], al[m][1], al[m][2], al[m][3], sb + T_ALO + aoff[m] + kb);
            }
            #pragma unroll
            for (int p = 0; p < 2; p++) {
                ldm_x4(bh[2*p][0], bh[2*p][1], bh[2*p+1][0], bh[2*p+1][1], sb + T_BHI + boff[p] + kb);
                ldm_x4(bl[2*p][0], bl[2*p][1], bl[2*p+1][0], bl[2*p+1][1], sb + T_BLO + boff[p] + kb);
            }
            #pragma unroll
            for (int m = 0; m < 2; m++)
                #pragma unroll
                for (int n = 0; n < 4; n++) {
                    mma_bf16(acc[m][n], ah[m], bh[n]);
                    mma_bf16(acc[m][n], al[m], bh[n]);
                    mma_bf16(acc[m][n], ah[m], bl[n]);
                }
        }
        __syncthreads();
    }

    const int fr  = lane >> 2;
    const int fc2 = (lane & 3) * 2;
    #pragma unroll
    for (int m = 0; m < 2; m++) {
        int row0 = wm * 32 + m * 16 + fr;
        #pragma unroll
        for (int n = 0; n < 4; n++) {
            int col = wn * 32 + n * 8 + fc2;
            float v0 = acc[m][n][0], v1 = acc[m][n][1];
            float v2 = acc[m][n][2], v3 = acc[m][n][3];
            if (BIAS) {
                float b0 = bias[col], b1 = bias[col + 1];
                v0 += b0; v1 += b1; v2 += b0; v3 += b1;
            }
            if (RES) {
                v0 += res[(size_t)row0 * ldc + col];
                v1 += res[(size_t)row0 * ldc + col + 1];
                v2 += res[(size_t)(row0 + 8) * ldc + col];
                v3 += res[(size_t)(row0 + 8) * ldc + col + 1];
            }
            C[(size_t)row0 * ldc + col]           = v0;
            C[(size_t)row0 * ldc + col + 1]       = v1;
            C[(size_t)(row0 + 8) * ldc + col]     = v2;
            C[(size_t)(row0 + 8) * ldc + col + 1] = v3;
        }
    }
}

// generic GEMM with residual (o-proj K=QD, down-proj K=F), N=H
__global__ void __launch_bounds__(512, 1)
mma_gemm_res(int K,
             const bf16* __restrict__ Ahi, const bf16* __restrict__ Alo,
             const bf16* __restrict__ Whi, const bf16* __restrict__ Wlo,
             const float* __restrict__ res, float* __restrict__ C) {
    extern __shared__ char smem[];
    const int bx = blockIdx.x, by = blockIdx.y;
    gemm_body<false, true>(K, H_,
                           Ahi + (size_t)by * 128 * K, Alo + (size_t)by * 128 * K,
                           Whi + (size_t)bx * 128 * K, Wlo + (size_t)bx * 128 * K,
                           nullptr,
                           res + (size_t)by * 128 * H_ + bx * 128,
                           C + (size_t)by * 128 * H_ + bx * 128,
                           smem);
}

// fused QKV projection: grid.x = 16 (12 q blocks, 2 k, 2 v); K = H
__global__ void __launch_bounds__(512, 1)
qkv_kernel(const bf16* __restrict__ Ahi, const bf16* __restrict__ Alo,
           const bf16* __restrict__ whi, const bf16* __restrict__ wlo,
           const float* __restrict__ bq, const float* __restrict__ bk,
           const float* __restrict__ bv,
           float* __restrict__ q, float* __restrict__ k, float* __restrict__ v) {
    extern __shared__ char smem[];
    const int bx = blockIdx.x, by = blockIdx.y;
    size_t seg; const float* bp; float* Cp; int ld, n0;
    if (bx < 12)      { seg = OFF_WQ; n0 = bx * 128;        bp = bq; Cp = q; ld = QD;  }
    else if (bx < 14) { seg = OFF_WK; n0 = (bx - 12) * 128; bp = bk; Cp = k; ld = KVD; }
    else              { seg = OFF_WV; n0 = (bx - 14) * 128; bp = bv; Cp = v; ld = KVD; }
    gemm_body<true, false>(H_, ld,
                           Ahi + (size_t)by * 128 * H_, Alo + (size_t)by * 128 * H_,
                           whi + seg + (size_t)n0 * H_, wlo + seg + (size_t)n0 * H_,
                           bp + n0, nullptr,
                           Cp + (size_t)by * 128 * ld + n0,
                           smem);
}

// ---------------- FUSED gate+up GEMM with silu epilogue ----------------
// Each CTA computes gate[128x128] and up[128x128] tiles sharing A, then writes
// split bf16 silu(gate)*up directly. 6 smem tensors per stage (216KB total).
#define GU_STAGE_B (6 * TILE_B)           // 110592
#define GU_SMEM (2 * GU_STAGE_B)          // 221184
#define T_GHI (2 * TILE_B)
#define T_GLO (3 * TILE_B)
#define T_UHI (4 * TILE_B)
#define T_ULO (5 * TILE_B)

__global__ void __launch_bounds__(512, 1)
gateup_kernel(const bf16* __restrict__ Ahi, const bf16* __restrict__ Alo,
              const bf16* __restrict__ whi, const bf16* __restrict__ wlo,  // layer base
              bf16* __restrict__ ohi, bf16* __restrict__ olo) {
    extern __shared__ char smem[];
    const int bx = blockIdx.x, by = blockIdx.y;
    const int n0 = bx * 128;

    const bf16* Agh = Ahi + (size_t)by * 128 * H_;
    const bf16* Agl = Alo + (size_t)by * 128 * H_;
    const bf16* Ggh = whi + OFF_WG + (size_t)n0 * H_;
    const bf16* Ggl = wlo + OFF_WG + (size_t)n0 * H_;
    const bf16* Ugh = whi + OFF_WU + (size_t)n0 * H_;
    const bf16* Ugl = wlo + OFF_WU + (size_t)n0 * H_;

    const int tid  = threadIdx.x;
    const int lane = tid & 31;
    const int wid  = tid >> 5;
    const int wm   = wid & 3;
    const int wn   = wid >> 2;

    const int row = tid >> 2;
    const int ch  = tid & 3;
    const size_t gRow = (size_t)row * H_ + ch * 8;
    const uint32_t sOff = (uint32_t)(row * TSTRIDE + ch * 16);

    const uint32_t smemBase = (uint32_t)__cvta_generic_to_shared(smem);

    const int lj = lane >> 3;
    const int lr = lane & 7;
    uint32_t aoff[2];
    #pragma unroll
    for (int m = 0; m < 2; m++)
        aoff[m] = (uint32_t)((wm * 32 + m * 16 + (lj & 1) * 8 + lr) * TSTRIDE + (lj >> 1) * 16);
    uint32_t boff[2];
    #pragma unroll
    for (int p = 0; p < 2; p++)
        boff[p] = (uint32_t)((wn * 32 + p * 16 + (lj >> 1) * 8 + lr) * TSTRIDE + (lj & 1) * 16);

    float gacc[2][4][4], uacc[2][4][4];
    #pragma unroll
    for (int m = 0; m < 2; m++)
        #pragma unroll
        for (int n = 0; n < 4; n++)
            #pragma unroll
            for (int r = 0; r < 4; r++) { gacc[m][n][r] = 0.f; uacc[m][n][r] = 0.f; }

    const int NT = H_ / 64;

    #pragma unroll
    for (int c = 0; c < 2; c++) {
        cp16(smem + T_AHI + sOff + c * 64, Agh + gRow + c * 32);
        cp16(smem + T_ALO + sOff + c * 64, Agl + gRow + c * 32);
        cp16(smem + T_GHI + sOff + c * 64, Ggh + gRow + c * 32);
        cp16(smem + T_GLO + sOff + c * 64, Ggl + gRow + c * 32);
        cp16(smem + T_UHI + sOff + c * 64, Ugh + gRow + c * 32);
        cp16(smem + T_ULO + sOff + c * 64, Ugl + gRow + c * 32);
    }
    asm volatile("cp.async.commit_group;");

    for (int t = 0; t < NT; t++) {
        if (t + 1 < NT) {
            char* s1 = smem + ((t + 1) & 1) * GU_STAGE_B;
            size_t g1 = gRow + (size_t)(t + 1) * 64;
            #pragma unroll
            for (int c = 0; c < 2; c++) {
                cp16(s1 + T_AHI + sOff + c * 64, Agh + g1 + c * 32);
                cp16(s1 + T_ALO + sOff + c * 64, Agl + g1 + c * 32);
                cp16(s1 + T_GHI + sOff + c * 64, Ggh + g1 + c * 32);
                cp16(s1 + T_GLO + sOff + c * 64, Ggl + g1 + c * 32);
                cp16(s1 + T_UHI + sOff + c * 64, Ugh + g1 + c * 32);
                cp16(s1 + T_ULO + sOff + c * 64, Ugl + g1 + c * 32);
            }
            asm volatile("cp.async.commit_group;");
            asm volatile("cp.async.wait_group 1;");
        } else {
            asm volatile("cp.async.wait_group 0;");
        }
        __syncthreads();

        const uint32_t sb = smemBase + (t & 1) * GU_STAGE_B;

        #pragma unroll
        for (int ks = 0; ks < 4; ks++) {
            const uint32_t kb = ks * 32;
            uint32_t ah[2][4], al[2][4];
            #pragma unroll
            for (int m = 0; m < 2; m++) {
                ldm_x4(ah[m][0], ah[m][1], ah[m][2], ah[m][3], sb + T_AHI + aoff[m] + kb);
                ldm_x4(al[m][0], al[m][1], al[m][2], al[m][3], sb + T_ALO + aoff[m] + kb);
            }
            {   // gate B frags
                uint32_t bh[4][2], bl[4][2];
                #pragma unroll
                for (int p = 0; p < 2; p++) {
                    ldm_x4(bh[2*p][0], bh[2*p][1], bh[2*p+1][0], bh[2*p+1][1], sb + T_GHI + boff[p] + kb);
                    ldm_x4(bl[2*p][0], bl[2*p][1], bl[2*p+1][0], bl[2*p+1][1], sb + T_GLO + boff[p] + kb);
                }
                #pragma unroll
                for (int m = 0; m < 2; m++)
                    #pragma unroll
                    for (int n = 0; n < 4; n++) {
                        mma_bf16(gacc[m][n], ah[m], bh[n]);
                        mma_bf16(gacc[m][n], al[m], bh[n]);
                        mma_bf16(gacc[m][n], ah[m], bl[n]);
                    }
            }
            {   // up B frags
                uint32_t bh[4][2], bl[4][2];
                #pragma unroll
                for (int p = 0; p < 2; p++) {
                    ldm_x4(bh[2*p][0], bh[2*p][1], bh[2*p+1][0], bh[2*p+1][1], sb + T_UHI + boff[p] + kb);
                    ldm_x4(bl[2*p][0], bl[2*p][1], bl[2*p+1][0], bl[2*p+1][1], sb + T_ULO + boff[p] + kb);
                }
                #pragma unroll
                for (int m = 0; m < 2; m++)
                    #pragma unroll
                    for (int n = 0; n < 4; n++) {
                        mma_bf16(uacc[m][n], ah[m], bh[n]);
                        mma_bf16(uacc[m][n], al[m], bh[n]);
                        mma_bf16(uacc[m][n], ah[m], bl[n]);
                    }
            }
        }
        __syncthreads();
    }

    // epilogue: silu(gate)*up -> split bf16
    const int fr  = lane >> 2;
    const int fc2 = (lane & 3) * 2;
    #pragma unroll
    for (int m = 0; m < 2; m++) {
        #pragma unroll
        for (int n = 0; n < 4; n++) {
            #pragma unroll
            for (int r = 0; r < 4; r++) {
                int row0 = by * 128 + wm * 32 + m * 16 + fr + ((r >> 1) ? 8 : 0);
                int col  = n0 + wn * 32 + n * 8 + fc2 + (r & 1);
                float g = gacc[m][n][r];
                float u = uacc[m][n][r];
                float val = (g / (1.f + __expf(-g))) * u;
                bf16 h, l; split1(val, h, l);
                size_t idx = (size_t)row0 * F_ + col;
                ohi[idx] = h;
                olo[idx] = l;
            }
        }
    }
}

// ---------------- RoPE (in place) ----------------
__global__ void rope_kernel(float* __restrict__ t, int nh) {
    int row = blockIdx.x;
    int tid = threadIdx.x;          // nh*64
    int hh = tid >> 6, d = tid & 63;
    int s = row % S_;
    float inv = expf(-(float)d * (13.815510557964274f / 64.0f));
    float ang = (float)s * inv;
    float sn, cs; sincosf(ang, &sn, &cs);
    float* p = t + (size_t)row * (nh * DH) + hh * DH + d;
    float x0 = p[0], x1 = p[64];
    p[0]  = x0 * cs - x1 * sn;
    p[64] = x1 * cs + x0 * sn;
}

// ---------------- attention: one block per (b, head, 16 q-rows), 128 threads ----------------
__global__ void __launch_bounds__(128, 3)
attn_kernel(const float* __restrict__ q,
            const float* __restrict__ k,
            const float* __restrict__ v,
            const int* __restrict__ mask,
            bf16* __restrict__ ohi, bf16* __restrict__ olo) {
    const int NQB = S_ / QT;
    int blk = blockIdx.x;
    int b   = blk / (NH * NQB);
    int rem = blk % (NH * NQB);
    int h   = rem / NQB;
    int q0  = (rem % NQB) * QT;
    int kvh = h / (NH / NKV);
    int tid = threadIdx.x;
    int lane = tid & 31, wrp = tid >> 5;

    __shared__ float qs[QT][DH];
    __shared__ float sc[QT][128];
    __shared__ float redm[QT][4];
    __shared__ float reds[QT][4];

    #pragma unroll
    for (int r = 0; r < QT; r++)
        qs[r][tid] = q[((size_t)(b * S_ + q0 + r)) * QD + h * DH + tid];
    __syncthreads();

    float m[QT], l[QT], acc[QT];
    #pragma unroll
    for (int r = 0; r < QT; r++) { m[r] = -1e30f; l[r] = 0.f; acc[r] = 0.f; }

    const float scale = 0.08838834764831845f;
    const int kend = q0 + QT;

    for (int kc = 0; kc < kend; kc += 128) {
        int j = kc + tid;
        bool jvalid = (j < kend) && (mask[b * S_ + j] > 0);
        float s[QT];
        if (jvalid) {
            const float4* kr = (const float4*)(k + ((size_t)(b * S_ + j)) * KVD + kvh * DH);
            float sum[QT];
            #pragma unroll
            for (int r = 0; r < QT; r++) sum[r] = 0.f;
            #pragma unroll 8
            for (int t4 = 0; t4 < 32; t4++) {
                float4 kk = kr[t4];
                #pragma unroll
                for (int r = 0; r < QT; r++) {
                    float4 qq = *(const float4*)&qs[r][t4 * 4];
                    sum[r] += qq.x * kk.x + qq.y * kk.y + qq.z * kk.z + qq.w * kk.w;
                }
            }
            #pragma unroll
            for (int r = 0; r < QT; r++)
                s[r] = (j <= q0 + r) ? sum[r] * scale : -1e30f;
        } else {
            #pragma unroll
            for (int r = 0; r < QT; r++) s[r] = -1e30f;
        }

        #pragma unroll
        for (int r = 0; r < QT; r++) {
            float wm = s[r];
            #pragma unroll
            for (int off = 16; off > 0; off >>= 1)
                wm = fmaxf(wm, __shfl_xor_sync(0xFFFFFFFF, wm, off));
            if (lane == 0) redm[r][wrp] = wm;
        }
        __syncthreads();

        float aph[QT];
        #pragma unroll
        for (int r = 0; r < QT; r++) {
            float cmax = fmaxf(fmaxf(redm[r][0], redm[r][1]), fmaxf(redm[r][2], redm[r][3]));
            float mnew = fmaxf(m[r], cmax);
            float pp = (s[r] > -1e29f) ? __expf(s[r] - mnew) : 0.f;
            sc[r][tid] = pp;
            float ws = pp;
            #pragma unroll
            for (int off = 16; off > 0; off >>= 1)
                ws += __shfl_xor_sync(0xFFFFFFFF, ws, off);
            if (lane == 0) reds[r][wrp] = ws;
            aph[r] = __expf(m[r] - mnew);
            m[r] = mnew;
        }
        __syncthreads();

        #pragma unroll
        for (int r = 0; r < QT; r++) {
            float psum = reds[r][0] + reds[r][1] + reds[r][2] + reds[r][3];
            l[r] = l[r] * aph[r] + psum;
            acc[r] *= aph[r];
        }

        int len = min(128, kend - kc);
        const float* vb = v + ((size_t)(b * S_ + kc)) * KVD + kvh * DH + tid;
        for (int jj = 0; jj < len; jj++) {
            float vv = vb[(size_t)jj * KVD];
            #pragma unroll
            for (int r = 0; r < QT; r++) acc[r] += sc[r][jj] * vv;
        }
        __syncthreads();
    }

    #pragma unroll
    for (int r = 0; r < QT; r++) {
        float o = acc[r] / l[r];
        bf16 hh2, ll2; split1(o, hh2, ll2);
        size_t idx = ((size_t)(b * S_ + q0 + r)) * QD + h * DH + tid;
        ohi[idx] = hh2;
        olo[idx] = ll2;
    }
}

// ---------------- last_hidden gather ----------------
__global__ void last_kernel(const int* __restrict__ mask,
                            const float* __restrict__ hidden,
                            float* __restrict__ out) {
    int b = blockIdx.x;
    int tid = threadIdx.x;
    __shared__ int red[256];
    int s = 0;
    for (int i = tid; i < S_; i += 256) s += mask[b * S_ + i];
    red[tid] = s; __syncthreads();
    for (int off = 128; off > 0; off >>= 1) {
        if (tid < off) red[tid] += red[tid + off];
        __syncthreads();
    }
    int pos = red[0] - 1;
    const float* hr = hidden + ((size_t)(b * S_ + pos)) * H_;
    for (int i = tid; i < H_; i += 256) out[(size_t)b * H_ + i] = hr[i];
}

extern "C" void kernel_launch(void* const* d_in, const int* in_sizes, int n_in,
                              void* d_out, int out_size) {
    const int*   ids  = (const int*)d_in[0];
    const int*   mask = (const int*)d_in[1];
    const float* emb  = (const float*)d_in[2];
    const float* wq   = (const float*)d_in[3];
    const float* bq   = (const float*)d_in[4];
    const float* wk   = (const float*)d_in[5];
    const float* bk   = (const float*)d_in[6];
    const float* wv   = (const float*)d_in[7];
    const float* bv   = (const float*)d_in[8];
    const float* wo   = (const float*)d_in[9];
    const float* wg   = (const float*)d_in[10];
    const float* wu   = (const float*)d_in[11];
    const float* wd   = (const float*)d_in[12];
    const float* ln1  = (const float*)d_in[13];
    const float* ln2  = (const float*)d_in[14];
    const float* lnf  = (const float*)d_in[15];
    float* out = (float*)d_out;

    float *x, *q, *k, *v;
    bf16 *hhi, *hlo, *ahi, *alo, *ghi, *glo, *whi, *wlo;
    cudaGetSymbolAddress((void**)&x,    g_x);
    cudaGetSymbolAddress((void**)&hhi,  g_hhi);
    cudaGetSymbolAddress((void**)&hlo,  g_hlo);
    cudaGetSymbolAddress((void**)&q,    g_q);
    cudaGetSymbolAddress((void**)&k,    g_k);
    cudaGetSymbolAddress((void**)&v,    g_v);
    cudaGetSymbolAddress((void**)&ahi,  g_ahi);
    cudaGetSymbolAddress((void**)&alo,  g_alo);
    cudaGetSymbolAddress((void**)&ghi,  g_ghi);
    cudaGetSymbolAddress((void**)&glo,  g_glo);
    cudaGetSymbolAddress((void**)&whi,  g_whi);
    cudaGetSymbolAddress((void**)&wlo,  g_wlo);

    static bool attr_set = false;
    if (!attr_set) {
        cudaFuncSetAttribute(qkv_kernel,
                             cudaFuncAttributeMaxDynamicSharedMemorySize, SMEM_BYTES);
        cudaFuncSetAttribute(gateup_kernel,
                             cudaFuncAttributeMaxDynamicSharedMemorySize, GU_SMEM);
        cudaFuncSetAttribute(mma_gemm_res,
                             cudaFuncAttributeMaxDynamicSharedMemorySize, SMEM_BYTES);
        attr_set = true;
    }

    // pre-split + transpose all weights (constant inputs)
    dim3 wb(32, 8);
    for (int l = 0; l < L_; l++) {
        bf16* Whi = whi + (size_t)l * WLAYER;
        bf16* Wlo = wlo + (size_t)l * WLAYER;
        wsplit_kernel<<<dim3(QD / 32, H_ / 64), wb>>>(wq + (size_t)l * H_ * QD,  H_, QD,  Whi + OFF_WQ, Wlo + OFF_WQ);
        wsplit_kernel<<<dim3(KVD / 32, H_ / 64), wb>>>(wk + (size_t)l * H_ * KVD, H_, KVD, Whi + OFF_WK, Wlo + OFF_WK);
        wsplit_kernel<<<dim3(KVD / 32, H_ / 64), wb>>>(wv + (size_t)l * H_ * KVD, H_, KVD, Whi + OFF_WV, Wlo + OFF_WV);
        wsplit_kernel<<<dim3(H_ / 32, QD / 64), wb>>>(wo + (size_t)l * QD * H_,  QD, H_,  Whi + OFF_WO, Wlo + OFF_WO);
        wsplit_kernel<<<dim3(F_ / 32, H_ / 64), wb>>>(wg + (size_t)l * H_ * F_,  H_, F_,  Whi + OFF_WG, Wlo + OFF_WG);
        wsplit_kernel<<<dim3(F_ / 32, H_ / 64), wb>>>(wu + (size_t)l * H_ * F_,  H_, F_,  Whi + OFF_WU, Wlo + OFF_WU);
        wsplit_kernel<<<dim3(H_ / 32, F_ / 64), wb>>>(wd + (size_t)l * F_ * H_,  F_, H_,  Whi + OFF_WD, Wlo + OFF_WD);
    }

    embed_kernel<<<ROWS, 256>>>(ids, emb, x);

    for (int l = 0; l < L_; l++) {
        const bf16* Whi = whi + (size_t)l * WLAYER;
        const bf16* Wlo = wlo + (size_t)l * WLAYER;

        rmsnorm_split_kernel<<<ROWS, 256>>>(x, ln1 + (size_t)l * H_, hhi, hlo);

        qkv_kernel<<<dim3(16, ROWS / 128), 512, SMEM_BYTES>>>(
            hhi, hlo, Whi, Wlo,
            bq + (size_t)l * QD, bk + (size_t)l * KVD, bv + (size_t)l * KVD,
            q, k, v);

        rope_kernel<<<ROWS, NH * 64>>>(q, NH);
        rope_kernel<<<ROWS, NKV * 64>>>(k, NKV);

        attn_kernel<<<B_ * NH * (S_ / QT), 128>>>(q, k, v, mask, ahi, alo);

        mma_gemm_res<<<dim3(H_ / 128, ROWS / 128), 512, SMEM_BYTES>>>(
            QD, ahi, alo, Whi + OFF_WO, Wlo + OFF_WO, x, x);

        rmsnorm_split_kernel<<<ROWS, 256>>>(x, ln2 + (size_t)l * H_, hhi, hlo);

        gateup_kernel<<<dim3(F_ / 128, ROWS / 128), 512, GU_SMEM>>>(
            hhi, hlo, Whi, Wlo, ghi, glo);

        mma_gemm_res<<<dim3(H_ / 128, ROWS / 128), 512, SMEM_BYTES>>>(
            F_, ghi, glo, Whi + OFF_WD, Wlo + OFF_WD, x, x);
    }

    rmsnorm_kernel<<<ROWS, 256>>>(x, lnf, out);
    last_kernel<<<B_, 256>>>(mask, out, out + (size_t)ROWS * H_);
}